// round 4
// baseline (speedup 1.0000x reference)
#include <cuda_runtime.h>
#include <cuda_bf16.h>
#include <cstdint>
#include <cfloat>

// GaussianLayer: out[m,k] = tanh(scale[k]) * exp(-zz - mm + 2*zm)
//   d[k,i]  = 0.1 + 0.9*sigmoid(diag[k,i]),  d in (0.1, 1.0)
//   exponent = -sum_i d[k,i]*(z[m,i]-mean[k,i])^2  <= 0 (exact identity)
// Weighted Cauchy-Schwarz (with d <= 1):
//   sum_i d*(z-mean)^2 >= (sqrt(mm[k]) - ||z_m||)^2  when sqrt(mm[k]) >= ||z_m||
// If sqrt(mm[k]) > ||z_m|| + 12, exponent < -144 < -104 => expf underflows
// to exactly +-0.0f, so the output element is exactly 0.0f.
// Global short-circuit: if max_m ||z_m|| + 12 < min_k sqrt(mm[k]), EVERY
// element underflows and the output kernel is a pure streaming memset.
// Otherwise fall back to per-row / per-element tests and, where the bound
// fails, the exact fp32 reference expression.

#define MAX_M 16384
#define MAX_OUT 2048

__device__ float g_zn[MAX_M];    // ||z_m||
__device__ float g_sq[MAX_OUT];  // sqrt(sum_i d*mean^2)
__device__ float g_ts[MAX_OUT];  // tanh(scale)
__device__ float g_minsq;        // min_k g_sq[k]
__device__ int   g_allzero;      // max_m g_zn + 12 < g_minsq

// ================= Kernel A: fused prep (row norms + k-stats) ============
__global__ void __launch_bounds__(256) prep_kernel(
    const float* __restrict__ z,
    const float* __restrict__ diag, const float* __restrict__ mean,
    const float* __restrict__ scale,
    int m, int out_f, int in_f, int nb_m)
{
    int wid_in_blk = threadIdx.x >> 5;
    int lane = threadIdx.x & 31;
    int n4 = in_f >> 2;

    if (blockIdx.x < nb_m) {
        // ---- row norm of z (8 independent float4 loads per lane) ----
        int row = blockIdx.x * 8 + wid_in_blk;
        if (row >= m) return;
        const float4* r = reinterpret_cast<const float4*>(z + (size_t)row * in_f);
        float s = 0.0f;
        if (n4 == 256) {
            float4 v[8];
            #pragma unroll
            for (int j = 0; j < 8; j++) v[j] = __ldcs(&r[lane + 32 * j]);
            #pragma unroll
            for (int j = 0; j < 8; j++)
                s += v[j].x * v[j].x + v[j].y * v[j].y
                   + v[j].z * v[j].z + v[j].w * v[j].w;
        } else {
            for (int i = lane; i < n4; i += 32) {
                float4 v = __ldcs(&r[i]);
                s += v.x * v.x + v.y * v.y + v.z * v.z + v.w * v.w;
            }
        }
        #pragma unroll
        for (int o = 16; o; o >>= 1) s += __shfl_xor_sync(0xFFFFFFFFu, s, o);
        if (lane == 0) g_zn[row] = sqrtf(s);
    } else {
        // ---- per-out-feature: sqrt(sum d*mean^2), tanh(scale) ----
        // Fast sigmoid feeds only the conservative bound (margin >> error);
        // the exact fallback never uses these values.
        int k = (blockIdx.x - nb_m) * 8 + wid_in_blk;
        if (k >= out_f) return;
        const float4* dr = reinterpret_cast<const float4*>(diag + (size_t)k * in_f);
        const float4* mr = reinterpret_cast<const float4*>(mean + (size_t)k * in_f);
        float s = 0.0f;
        #pragma unroll 4
        for (int i = lane; i < n4; i += 32) {
            float4 dv = __ldcs(&dr[i]);
            float4 mv = __ldcs(&mr[i]);
            float d0 = 0.1f + __fdividef(0.9f, 1.0f + __expf(-dv.x));
            float d1 = 0.1f + __fdividef(0.9f, 1.0f + __expf(-dv.y));
            float d2 = 0.1f + __fdividef(0.9f, 1.0f + __expf(-dv.z));
            float d3 = 0.1f + __fdividef(0.9f, 1.0f + __expf(-dv.w));
            s += d0 * mv.x * mv.x + d1 * mv.y * mv.y
               + d2 * mv.z * mv.z + d3 * mv.w * mv.w;
        }
        #pragma unroll
        for (int o = 16; o; o >>= 1) s += __shfl_xor_sync(0xFFFFFFFFu, s, o);
        if (lane == 0) {
            g_sq[k] = sqrtf(s);
            g_ts[k] = tanhf(scale[k]);
        }
    }
}

// ========== Kernel C: single-block reduce (min g_sq, max g_zn, flag) ======
__global__ void __launch_bounds__(1024) reduce_kernel(int m, int out_f)
{
    __shared__ float s_min[32];
    __shared__ float s_max[32];
    int tid = threadIdx.x;
    int lane = tid & 31;
    int wid = tid >> 5;

    float lmin = FLT_MAX;
    for (int k = tid; k < out_f; k += 1024) lmin = fminf(lmin, g_sq[k]);
    float lmax = 0.0f;
    for (int i = tid; i < m; i += 1024) lmax = fmaxf(lmax, g_zn[i]);

    #pragma unroll
    for (int o = 16; o; o >>= 1) {
        lmin = fminf(lmin, __shfl_xor_sync(0xFFFFFFFFu, lmin, o));
        lmax = fmaxf(lmax, __shfl_xor_sync(0xFFFFFFFFu, lmax, o));
    }
    if (lane == 0) { s_min[wid] = lmin; s_max[wid] = lmax; }
    __syncthreads();
    if (tid == 0) {
        float mn = s_min[0], mx = s_max[0];
        #pragma unroll
        for (int i = 1; i < 32; i++) {
            mn = fminf(mn, s_min[i]);
            mx = fmaxf(mx, s_max[i]);
        }
        g_minsq = mn;
        g_allzero = (mx + 12.0f < mn) ? 1 : 0;
    }
}

// ================= Fallback: exact fp32 reference expression ==============
__device__ __noinline__ float slow_elem(
    const float* __restrict__ z, const float* __restrict__ diag,
    const float* __restrict__ mean, int mrow, int k, int in_f)
{
    const float* zr = z + (size_t)mrow * in_f;
    const float* dr = diag + (size_t)k * in_f;
    const float* mr = mean + (size_t)k * in_f;
    float zz = 0.0f, zm = 0.0f, mm = 0.0f;
    for (int i = 0; i < in_f; i++) {
        float d = 0.1f + 0.9f / (1.0f + expf(-dr[i]));
        float zi = zr[i];
        float mi = mr[i];
        zz += d * zi * zi;
        zm += zi * d * mi;
        mm += d * mi * mi;
    }
    return g_ts[k] * expf(-zz - mm + 2.0f * zm);
}

// ================= Kernel B: output =======================================
// Fast path (g_allzero): pure streaming memset -- 16 independent STG.128.cs
// per thread, no loads, no row math. Slow path: per-row min-test, then
// per-element bound test + exact fallback.
#define OU 16

__global__ void __launch_bounds__(256) out_kernel(
    const float* __restrict__ z, const float* __restrict__ diag,
    const float* __restrict__ mean, float* __restrict__ out,
    int m, int out_f, int in_f, int n4row, int n4tot, int row_shift)
{
    float4* out4 = reinterpret_cast<float4*>(out);
    const float4 zero4 = make_float4(0.0f, 0.0f, 0.0f, 0.0f);
    int base = blockIdx.x * (256 * OU) + threadIdx.x;

    if (g_allzero) {
        #pragma unroll
        for (int j = 0; j < OU; j++) {
            int idx = base + j * 256;
            if (idx < n4tot) __stcs(&out4[idx], zero4);
        }
        return;
    }

    // ---------------- slow path (flag false) ----------------
    float minsq = g_minsq;
    #pragma unroll
    for (int j = 0; j < OU; j++) {
        int idx = base + j * 256;
        if (idx >= n4tot) continue;
        int row = (row_shift >= 0) ? (idx >> row_shift)
                                   : (int)((unsigned)idx / (unsigned)n4row);
        float thr = g_zn[row] + 12.0f;
        if (minsq > thr) {
            __stcs(&out4[idx], zero4);
        } else {
            int kbase = (idx - row * n4row) * 4;
            float4 r4;
            float* rp = &r4.x;
            #pragma unroll
            for (int e = 0; e < 4; e++) {
                int k = kbase + e;
                rp[e] = (g_sq[k] > thr)
                            ? 0.0f
                            : slow_elem(z, diag, mean, row, k, in_f);
            }
            out4[idx] = r4;
        }
    }
}

extern "C" void kernel_launch(void* const* d_in, const int* in_sizes, int n_in,
                              void* d_out, int out_size)
{
    const float* z     = (const float*)d_in[0];  // (m, in_f)
    const float* diag  = (const float*)d_in[1];  // (out_f, in_f)
    const float* mean  = (const float*)d_in[2];  // (out_f, in_f, 1)
    const float* scale = (const float*)d_in[3];  // (out_f,)
    float* out = (float*)d_out;

    int out_f = in_sizes[3];
    int in_f  = in_sizes[1] / out_f;
    int m     = in_sizes[0] / in_f;

    // Kernel A: fused prep (row norms + k stats)
    int nb_m = (m + 7) / 8;
    int nb_k = (out_f + 7) / 8;
    prep_kernel<<<nb_m + nb_k, 256>>>(z, diag, mean, scale, m, out_f, in_f, nb_m);

    // Kernel C: global reductions + all-zero flag
    reduce_kernel<<<1, 1024>>>(m, out_f);

    // Kernel B: output
    int n4row = out_f >> 2;
    int n4tot = (int)(((size_t)m * out_f) >> 2);
    int row_shift = -1;
    if ((n4row & (n4row - 1)) == 0) {
        row_shift = 0;
        while ((1 << row_shift) != n4row) row_shift++;
    }
    int per_block = 256 * OU;
    int nb_out = (n4tot + per_block - 1) / per_block;
    out_kernel<<<nb_out, 256>>>(z, diag, mean, out, m, out_f, in_f,
                                n4row, n4tot, row_shift);
}